// round 1
// baseline (speedup 1.0000x reference)
#include <cuda_runtime.h>
#include <cuda_bf16.h>
#include <cstdint>

#define NTOK 2048
#define DDIM 1024
#define NEXP 8
#define SEG  2048
#define LDSB 18   // smem row stride in bf16 (conflict-free for quad access)

// ---------------- scratch (static device globals; no allocation) -------------
__device__ float g_hid_sh[NTOK * DDIM];          // shared-expert hidden (8 MB)
__device__ float g_hid_ex[NEXP * SEG * DDIM];    // routed hidden, padded segs (64 MB)
__device__ int   g_cnt[NEXP];
__device__ int   g_tok[NEXP * SEG];
__device__ float g_gw[NEXP * SEG];

__global__ void zero_cnt_kernel() {
    if (threadIdx.x < NEXP) g_cnt[threadIdx.x] = 0;
}

// ---------------- router: exact fp32 logits, top-2, sigmoid gating -----------
__global__ void router_kernel(const float* __restrict__ x,
                              const float* __restrict__ gate_w,
                              const float* __restrict__ lb_bias) {
    __shared__ float lg[NEXP];
    int n = blockIdx.x;
    int e = threadIdx.x >> 5, lane = threadIdx.x & 31;
    const float* xr = x + (size_t)n * DDIM;
    const float* w  = gate_w + (size_t)e * DDIM;
    float s = 0.f;
    #pragma unroll 4
    for (int d = lane; d < DDIM; d += 32) s += xr[d] * w[d];
    #pragma unroll
    for (int o = 16; o; o >>= 1) s += __shfl_xor_sync(0xffffffffu, s, o);
    if (lane == 0) lg[e] = s;
    __syncthreads();
    if (threadIdx.x == 0) {
        float b1v = -1e30f; int b1 = 0;
        #pragma unroll
        for (int i = 0; i < NEXP; i++) {
            float v = lg[i] + lb_bias[i];
            if (v > b1v) { b1v = v; b1 = i; }
        }
        float b2v = -1e30f; int b2 = 0;
        #pragma unroll
        for (int i = 0; i < NEXP; i++) {
            if (i == b1) continue;
            float v = lg[i] + lb_bias[i];
            if (v > b2v) { b2v = v; b2 = i; }
        }
        float w1 = 1.f / (1.f + expf(-lg[b1]));
        float w2 = 1.f / (1.f + expf(-lg[b2]));
        float inv = 1.f / (w1 + w2 + 1e-6f);
        w1 *= inv; w2 *= inv;
        int p1 = atomicAdd(&g_cnt[b1], 1);
        g_tok[b1 * SEG + p1] = n; g_gw[b1 * SEG + p1] = w1;
        int p2 = atomicAdd(&g_cnt[b2], 1);
        g_tok[b2 * SEG + p2] = n; g_gw[b2 * SEG + p2] = w2;
    }
}

// ---------------- split-bf16 GEMM (3-term: hi*hi + hi*lo + lo*hi) ------------
// MODE 0: shared GEMM1: A=x,        B=cfc,     epi relu^2 -> g_hid_sh
// MODE 1: shared GEMM2: A=g_hid_sh, B=cproj,   epi store  -> out
// MODE 2: expert GEMM1: A=gather(x),B=w1[e],   epi relu^2 -> g_hid_ex seg
// MODE 3: expert GEMM2: A=hid seg,  B=w2[e],   epi gw*atomicAdd -> out

#define MMA_BF16(c, a, bb0, bb1)                                               \
    asm volatile(                                                              \
        "mma.sync.aligned.m16n8k16.row.col.f32.bf16.bf16.f32 "                 \
        "{%0,%1,%2,%3},{%4,%5,%6,%7},{%8,%9},{%0,%1,%2,%3};\n"                 \
        : "+f"((c)[0]), "+f"((c)[1]), "+f"((c)[2]), "+f"((c)[3])               \
        : "r"((a)[0]), "r"((a)[1]), "r"((a)[2]), "r"((a)[3]),                  \
          "r"(bb0), "r"(bb1))

__device__ __forceinline__ uint32_t lds32(const __nv_bfloat16* p) {
    return *reinterpret_cast<const uint32_t*>(p);
}

__device__ __forceinline__ void store_split(float f, __nv_bfloat16* hi,
                                            __nv_bfloat16* lo, int idx) {
    __nv_bfloat16 h = __float2bfloat16(f);
    float rem = f - __bfloat162float(h);
    hi[idx] = h;
    lo[idx] = __float2bfloat16(rem);
}

template <int MODE>
__global__ __launch_bounds__(256)
void gemm_moe_kernel(const float* __restrict__ A, const float* __restrict__ Bm,
                     float* __restrict__ C) {
    __shared__ __align__(16) __nv_bfloat16 sAh[128 * LDSB];
    __shared__ __align__(16) __nv_bfloat16 sAl[128 * LDSB];
    __shared__ __align__(16) __nv_bfloat16 sBh[128 * LDSB];
    __shared__ __align__(16) __nv_bfloat16 sBl[128 * LDSB];

    const int e   = blockIdx.z;
    const int seg = e * SEG;
    int cnt = NTOK;
    const float* Abase = A;
    const float* Bbase = Bm;
    if (MODE == 1) Abase = g_hid_sh;
    if (MODE == 2) { cnt = g_cnt[e]; Bbase = Bm + (size_t)e * DDIM * DDIM; }
    if (MODE == 3) {
        cnt = g_cnt[e];
        Bbase = Bm + (size_t)e * DDIM * DDIM;
        Abase = g_hid_ex + (size_t)e * SEG * DDIM;
    }
    const int m0 = blockIdx.y * 128;
    if ((MODE >= 2) && m0 >= cnt) return;
    const int n0 = blockIdx.x * 128;

    const int tid  = threadIdx.x;
    const int wid  = tid >> 5, lane = tid & 31;
    const int wm   = (wid & 3) * 32, wn = (wid >> 2) * 64;
    const int q    = lane & 3, g = lane >> 2;

    // per-thread load rows (2 A rows, 2 B rows; each thread handles 2 float4/array)
    const int rA0 = tid >> 2, rA1 = rA0 + 64;
    const int kq4 = (tid & 3) * 4;

    const float* aptr0;
    const float* aptr1;
    if (MODE == 2) {
        int r0 = m0 + rA0, r1 = m0 + rA1;
        int t0 = g_tok[seg + (r0 < cnt ? r0 : 0)];
        int t1 = g_tok[seg + (r1 < cnt ? r1 : 0)];
        aptr0 = A + (size_t)t0 * DDIM;
        aptr1 = A + (size_t)t1 * DDIM;
    } else {
        aptr0 = Abase + (size_t)(m0 + rA0) * DDIM;
        aptr1 = Abase + (size_t)(m0 + rA1) * DDIM;
    }
    const float* bptr0 = Bbase + (size_t)(n0 + rA0) * DDIM;
    const float* bptr1 = Bbase + (size_t)(n0 + rA1) * DDIM;

    float acc[2][8][4];
    #pragma unroll
    for (int mi = 0; mi < 2; mi++)
        #pragma unroll
        for (int ni = 0; ni < 8; ni++)
            #pragma unroll
            for (int j = 0; j < 4; j++) acc[mi][ni][j] = 0.f;

    for (int kt = 0; kt < DDIM / 16; kt++) {
        const int kk = kt * 16 + kq4;
        float4 va0 = *reinterpret_cast<const float4*>(aptr0 + kk);
        float4 va1 = *reinterpret_cast<const float4*>(aptr1 + kk);
        float4 vb0 = *reinterpret_cast<const float4*>(bptr0 + kk);
        float4 vb1 = *reinterpret_cast<const float4*>(bptr1 + kk);

        __syncthreads();  // previous tile fully consumed
        #pragma unroll
        for (int j = 0; j < 4; j++) {
            store_split((&va0.x)[j], sAh, sAl, rA0 * LDSB + kq4 + j);
            store_split((&va1.x)[j], sAh, sAl, rA1 * LDSB + kq4 + j);
            store_split((&vb0.x)[j], sBh, sBl, rA0 * LDSB + kq4 + j);
            store_split((&vb1.x)[j], sBh, sBl, rA1 * LDSB + kq4 + j);
        }
        __syncthreads();

        uint32_t ah[2][4], al[2][4];
        #pragma unroll
        for (int mi = 0; mi < 2; mi++) {
            int rb = wm + mi * 16 + g;
            ah[mi][0] = lds32(&sAh[rb * LDSB + 2 * q]);
            ah[mi][1] = lds32(&sAh[(rb + 8) * LDSB + 2 * q]);
            ah[mi][2] = lds32(&sAh[rb * LDSB + 8 + 2 * q]);
            ah[mi][3] = lds32(&sAh[(rb + 8) * LDSB + 8 + 2 * q]);
            al[mi][0] = lds32(&sAl[rb * LDSB + 2 * q]);
            al[mi][1] = lds32(&sAl[(rb + 8) * LDSB + 2 * q]);
            al[mi][2] = lds32(&sAl[rb * LDSB + 8 + 2 * q]);
            al[mi][3] = lds32(&sAl[(rb + 8) * LDSB + 8 + 2 * q]);
        }
        #pragma unroll
        for (int ni = 0; ni < 8; ni++) {
            int nb = wn + ni * 8 + g;
            uint32_t bh0 = lds32(&sBh[nb * LDSB + 2 * q]);
            uint32_t bh1 = lds32(&sBh[nb * LDSB + 8 + 2 * q]);
            uint32_t bl0 = lds32(&sBl[nb * LDSB + 2 * q]);
            uint32_t bl1 = lds32(&sBl[nb * LDSB + 8 + 2 * q]);
            #pragma unroll
            for (int mi = 0; mi < 2; mi++) {
                MMA_BF16(acc[mi][ni], ah[mi], bh0, bh1);
                MMA_BF16(acc[mi][ni], ah[mi], bl0, bl1);
                MMA_BF16(acc[mi][ni], al[mi], bh0, bh1);
            }
        }
    }

    // -------- epilogue --------
    #pragma unroll
    for (int mi = 0; mi < 2; mi++) {
        int rr0 = m0 + wm + mi * 16 + g;   // row (segment-local for MODE 2/3)
        int rr1 = rr0 + 8;
        int tok0 = 0, tok1 = 0;
        float gw0 = 0.f, gw1 = 0.f;
        if (MODE == 3) {
            if (rr0 < cnt) { tok0 = g_tok[seg + rr0]; gw0 = g_gw[seg + rr0]; }
            if (rr1 < cnt) { tok1 = g_tok[seg + rr1]; gw1 = g_gw[seg + rr1]; }
        }
        #pragma unroll
        for (int ni = 0; ni < 8; ni++) {
            int cg = n0 + wn + ni * 8 + 2 * q;
            float v0 = acc[mi][ni][0], v1 = acc[mi][ni][1];
            float v2 = acc[mi][ni][2], v3 = acc[mi][ni][3];
            if (MODE == 0) {
                float r0 = fmaxf(v0, 0.f), r1 = fmaxf(v1, 0.f);
                float r2 = fmaxf(v2, 0.f), r3 = fmaxf(v3, 0.f);
                g_hid_sh[(size_t)rr0 * DDIM + cg]     = r0 * r0;
                g_hid_sh[(size_t)rr0 * DDIM + cg + 1] = r1 * r1;
                g_hid_sh[(size_t)rr1 * DDIM + cg]     = r2 * r2;
                g_hid_sh[(size_t)rr1 * DDIM + cg + 1] = r3 * r3;
            } else if (MODE == 1) {
                C[(size_t)rr0 * DDIM + cg]     = v0;
                C[(size_t)rr0 * DDIM + cg + 1] = v1;
                C[(size_t)rr1 * DDIM + cg]     = v2;
                C[(size_t)rr1 * DDIM + cg + 1] = v3;
            } else if (MODE == 2) {
                float* hb = g_hid_ex + (size_t)e * SEG * DDIM;
                if (rr0 < cnt) {
                    float r0 = fmaxf(v0, 0.f), r1 = fmaxf(v1, 0.f);
                    hb[(size_t)rr0 * DDIM + cg]     = r0 * r0;
                    hb[(size_t)rr0 * DDIM + cg + 1] = r1 * r1;
                }
                if (rr1 < cnt) {
                    float r2 = fmaxf(v2, 0.f), r3 = fmaxf(v3, 0.f);
                    hb[(size_t)rr1 * DDIM + cg]     = r2 * r2;
                    hb[(size_t)rr1 * DDIM + cg + 1] = r3 * r3;
                }
            } else {  // MODE 3
                if (rr0 < cnt) {
                    atomicAdd(&C[(size_t)tok0 * DDIM + cg],     gw0 * v0);
                    atomicAdd(&C[(size_t)tok0 * DDIM + cg + 1], gw0 * v1);
                }
                if (rr1 < cnt) {
                    atomicAdd(&C[(size_t)tok1 * DDIM + cg],     gw1 * v2);
                    atomicAdd(&C[(size_t)tok1 * DDIM + cg + 1], gw1 * v3);
                }
            }
        }
    }
}

// ---------------- launch -----------------------------------------------------
extern "C" void kernel_launch(void* const* d_in, const int* in_sizes, int n_in,
                              void* d_out, int out_size) {
    const float* x      = (const float*)d_in[0];  // (2,1024,1024)
    const float* gate_w = (const float*)d_in[1];  // (8,1024)
    const float* lbias  = (const float*)d_in[2];  // (8,)
    const float* w1     = (const float*)d_in[3];  // (8,1024,1024)
    const float* w2     = (const float*)d_in[4];  // (8,1024,1024)
    const float* cfc    = (const float*)d_in[5];  // (1024,1024)
    const float* cproj  = (const float*)d_in[6];  // (1024,1024)
    float* out = (float*)d_out;                   // (2,1024,1024)

    zero_cnt_kernel<<<1, 32>>>();
    router_kernel<<<NTOK, 256>>>(x, gate_w, lbias);

    dim3 blk(256);
    dim3 grid_sh(8, NTOK / 128, 1);
    dim3 grid_ex(8, SEG / 128, NEXP);

    // shared expert: writes full out (covers the 0xAA poison)
    gemm_moe_kernel<0><<<grid_sh, blk>>>(x, cfc, nullptr);
    gemm_moe_kernel<1><<<grid_sh, blk>>>(x, cproj, out);
    // routed experts: relu^2 hidden then weighted scatter-add
    gemm_moe_kernel<2><<<grid_ex, blk>>>(x, w1, nullptr);
    gemm_moe_kernel<3><<<grid_ex, blk>>>(nullptr, w2, out);
}

// round 3
// speedup vs baseline: 1.1364x; 1.1364x over previous
#include <cuda_runtime.h>
#include <cuda_bf16.h>
#include <cstdint>

#define NTOK 2048
#define DDIM 1024
#define NEXP 8
#define SEG  2048

typedef __nv_bfloat16 bf16;

// ---------------- scratch (static device globals; no allocation) -------------
__device__ bf16 g_xh[NTOK * DDIM];
__device__ bf16 g_xl[NTOK * DDIM];
__device__ bf16 g_hsh_h[NTOK * DDIM];
__device__ bf16 g_hsh_l[NTOK * DDIM];
__device__ bf16 g_hex_h[NEXP * SEG * DDIM];
__device__ bf16 g_hex_l[NEXP * SEG * DDIM];
__device__ bf16 g_w1h[NEXP * DDIM * DDIM];
__device__ bf16 g_w1l[NEXP * DDIM * DDIM];
__device__ bf16 g_w2h[NEXP * DDIM * DDIM];
__device__ bf16 g_w2l[NEXP * DDIM * DDIM];
__device__ bf16 g_cfch[DDIM * DDIM];
__device__ bf16 g_cfcl[DDIM * DDIM];
__device__ bf16 g_cpjh[DDIM * DDIM];
__device__ bf16 g_cpjl[DDIM * DDIM];
__device__ int   g_cnt[NEXP];
__device__ int   g_tok[NEXP * SEG];
__device__ float g_gw[NEXP * SEG];

// ---------------- small kernels ----------------------------------------------
__global__ void zero_cnt_kernel() {
    if (threadIdx.x < NEXP) g_cnt[threadIdx.x] = 0;
}

__global__ void split_kernel(const float* __restrict__ src,
                             bf16* __restrict__ h, bf16* __restrict__ l) {
    int i = (blockIdx.x * blockDim.x + threadIdx.x) * 4;
    float4 v = *reinterpret_cast<const float4*>(src + i);
    bf16 hh[4], ll[4];
    #pragma unroll
    for (int j = 0; j < 4; j++) {
        float f = (&v.x)[j];
        bf16 hv = __float2bfloat16(f);
        hh[j] = hv;
        ll[j] = __float2bfloat16(f - __bfloat162float(hv));
    }
    *reinterpret_cast<uint2*>(h + i) = *reinterpret_cast<uint2*>(hh);
    *reinterpret_cast<uint2*>(l + i) = *reinterpret_cast<uint2*>(ll);
}

__global__ void router_kernel(const float* __restrict__ x,
                              const float* __restrict__ gate_w,
                              const float* __restrict__ lb_bias) {
    __shared__ float lg[NEXP];
    int n = blockIdx.x;
    int e = threadIdx.x >> 5, lane = threadIdx.x & 31;
    const float* xr = x + (size_t)n * DDIM;
    const float* w  = gate_w + (size_t)e * DDIM;
    float s = 0.f;
    #pragma unroll 4
    for (int d = lane; d < DDIM; d += 32) s += xr[d] * w[d];
    #pragma unroll
    for (int o = 16; o; o >>= 1) s += __shfl_xor_sync(0xffffffffu, s, o);
    if (lane == 0) lg[e] = s;
    __syncthreads();
    if (threadIdx.x == 0) {
        float b1v = -1e30f; int b1 = 0;
        #pragma unroll
        for (int i = 0; i < NEXP; i++) {
            float v = lg[i] + lb_bias[i];
            if (v > b1v) { b1v = v; b1 = i; }
        }
        float b2v = -1e30f; int b2 = 0;
        #pragma unroll
        for (int i = 0; i < NEXP; i++) {
            if (i == b1) continue;
            float v = lg[i] + lb_bias[i];
            if (v > b2v) { b2v = v; b2 = i; }
        }
        float w1 = 1.f / (1.f + expf(-lg[b1]));
        float w2 = 1.f / (1.f + expf(-lg[b2]));
        float inv = 1.f / (w1 + w2 + 1e-6f);
        w1 *= inv; w2 *= inv;
        int p1 = atomicAdd(&g_cnt[b1], 1);
        g_tok[b1 * SEG + p1] = n; g_gw[b1 * SEG + p1] = w1;
        int p2 = atomicAdd(&g_cnt[b2], 1);
        g_tok[b2 * SEG + p2] = n; g_gw[b2 * SEG + p2] = w2;
    }
}

// ---------------- pipelined mma.sync GEMM ------------------------------------
// BM=128, BN=128, BK=32, 3-stage cp.async, 8 warps, warp tile 32x64.
// 3-term bf16 split: AhBh + AhBl + AlBh.
// MODE 1: phase1 fused   (shared GEMM1 + expert GEMM1) -> relu^2 split store
// MODE 2: shared GEMM2   -> plain store to out (covers poison)
// MODE 3: expert GEMM2   -> gw * atomicAdd into out

#define ROWB   80                 // padded row stride bytes (32 bf16 + 16B pad)
#define REG_AL 10240              // region offsets within a stage
#define REG_BH 20480
#define REG_BL 30720
#define STAGE_B 40960
#define SMEM_GEMM (3 * STAGE_B)

#define CP16(sm, gp) \
    asm volatile("cp.async.cg.shared.global [%0], [%1], 16;" \
                 :: "r"(sm), "l"(gp) : "memory")
#define CP_COMMIT() asm volatile("cp.async.commit_group;" ::: "memory")
#define CP_WAIT1()  asm volatile("cp.async.wait_group 1;" ::: "memory")

#define LDSM4(r, a) \
    asm volatile("ldmatrix.sync.aligned.m8n8.x4.shared.b16 {%0,%1,%2,%3}, [%4];" \
                 : "=r"((r)[0]), "=r"((r)[1]), "=r"((r)[2]), "=r"((r)[3]) \
                 : "r"(a))

#define MMA_BF16(c, a, bb0, bb1)                                               \
    asm volatile(                                                              \
        "mma.sync.aligned.m16n8k16.row.col.f32.bf16.bf16.f32 "                 \
        "{%0,%1,%2,%3},{%4,%5,%6,%7},{%8,%9},{%0,%1,%2,%3};\n"                 \
        : "+f"((c)[0]), "+f"((c)[1]), "+f"((c)[2]), "+f"((c)[3])               \
        : "r"((a)[0]), "r"((a)[1]), "r"((a)[2]), "r"((a)[3]),                  \
          "r"(bb0), "r"(bb1))

__device__ __forceinline__ uint32_t smem_u32(const void* p) {
    uint32_t a;
    asm("{ .reg .u64 t; cvta.to.shared.u64 t, %1; cvt.u32.u64 %0, t; }"
        : "=r"(a) : "l"(p));
    return a;
}

template <int MODE>
__global__ __launch_bounds__(256, 1)
void gemm_mma(float* __restrict__ C) {
    extern __shared__ char dsm[];
    const int tid = threadIdx.x;
    const int wid = tid >> 5, lane = tid & 31;
    const int wm = (wid & 3) * 32, wn = (wid >> 2) * 64;

    bool sh;
    int e = 0, m0, cnt;
    if (MODE == 1) sh = (blockIdx.y < 16);
    else if (MODE == 2) sh = true;
    else sh = false;

    const bf16 *Ah, *Al, *Bh, *Bl;
    if (sh) {
        m0 = (MODE == 1 ? blockIdx.y : blockIdx.y) * 128;
        cnt = NTOK;
        if (MODE == 1) { Ah = g_xh;    Al = g_xl;    Bh = g_cfch; Bl = g_cfcl; }
        else           { Ah = g_hsh_h; Al = g_hsh_l; Bh = g_cpjh; Bl = g_cpjl; }
    } else {
        int yb = (MODE == 1) ? (blockIdx.y - 16) : blockIdx.y;
        e = yb >> 4;
        m0 = (yb & 15) * 128;
        cnt = g_cnt[e];
        if (m0 >= cnt) return;
        size_t wo = (size_t)e * DDIM * DDIM;
        if (MODE == 1) { Ah = g_xh; Al = g_xl; Bh = g_w1h + wo; Bl = g_w1l + wo; }
        else { Ah = g_hex_h + (size_t)e * SEG * DDIM;
               Al = g_hex_l + (size_t)e * SEG * DDIM;
               Bh = g_w2h + wo; Bl = g_w2l + wo; }
    }
    const int n0 = blockIdx.x * 128;

    // per-thread load assignment: row lr (0..127), two 16B chunks at lc0, lc0+1
    const int lr = tid >> 1;
    const int lc0 = (tid & 1) * 2;
    const bf16 *pAh, *pAl;
    if (MODE == 1 && !sh) {
        int rr = m0 + lr;
        int tok = g_tok[e * SEG + (rr < cnt ? rr : 0)];
        pAh = g_xh + (size_t)tok * DDIM;
        pAl = g_xl + (size_t)tok * DDIM;
    } else {
        pAh = Ah + (size_t)(m0 + lr) * DDIM;
        pAl = Al + (size_t)(m0 + lr) * DDIM;
    }
    const bf16* pBh = Bh + (size_t)(n0 + lr) * DDIM;
    const bf16* pBl = Bl + (size_t)(n0 + lr) * DDIM;

    const uint32_t su = smem_u32(dsm);
    const uint32_t wbase = lr * ROWB + lc0 * 16;   // store offset within region

    // ldmatrix per-lane offsets
    const uint32_t aoff = (uint32_t)((wm + (lane & 15)) * ROWB + (lane >> 4) * 16);
    const int brow = (lane & 7) | ((lane & 16) >> 1);
    const uint32_t boff = (uint32_t)((wn + brow) * ROWB + ((lane >> 3) & 1) * 16);

    float acc[2][8][4];
    #pragma unroll
    for (int mi = 0; mi < 2; mi++)
        #pragma unroll
        for (int ni = 0; ni < 8; ni++)
            #pragma unroll
            for (int j = 0; j < 4; j++) acc[mi][ni][j] = 0.f;

    // ---- pipeline ----
    #define ISSUE(kt, st) do {                                                 \
        uint32_t sb = su + (st) * STAGE_B + wbase;                             \
        const bf16* ga = pAh + (kt) * 32 + lc0 * 8;                            \
        CP16(sb, ga); CP16(sb + 16, ga + 8);                                   \
        const bf16* gal = pAl + (kt) * 32 + lc0 * 8;                           \
        CP16(sb + REG_AL, gal); CP16(sb + REG_AL + 16, gal + 8);               \
        const bf16* gb = pBh + (kt) * 32 + lc0 * 8;                            \
        CP16(sb + REG_BH, gb); CP16(sb + REG_BH + 16, gb + 8);                 \
        const bf16* gbl = pBl + (kt) * 32 + lc0 * 8;                           \
        CP16(sb + REG_BL, gbl); CP16(sb + REG_BL + 16, gbl + 8);               \
    } while (0)

    ISSUE(0, 0); CP_COMMIT();
    ISSUE(1, 1); CP_COMMIT();

    int st = 0;
    for (int kt = 0; kt < 32; kt++) {
        CP_WAIT1();
        __syncthreads();
        int st2 = st + 2; if (st2 >= 3) st2 -= 3;
        if (kt < 30) ISSUE(kt + 2, st2);
        CP_COMMIT();

        const uint32_t sA = su + st * STAGE_B;
        const uint32_t sB = sA + REG_BH;
        #pragma unroll
        for (int s = 0; s < 2; s++) {
            uint32_t ah[2][4], al[2][4];
            #pragma unroll
            for (int mi = 0; mi < 2; mi++) {
                uint32_t a = sA + aoff + mi * (16 * ROWB) + s * 32;
                LDSM4(ah[mi], a);
                LDSM4(al[mi], a + REG_AL);
            }
            #pragma unroll
            for (int j = 0; j < 4; j++) {
                uint32_t bh[4], bl[4];
                uint32_t b = sB + boff + j * (16 * ROWB) + s * 32;
                LDSM4(bh, b);
                LDSM4(bl, b + REG_AL);   // BL region is BH + 10240
                #pragma unroll
                for (int mi = 0; mi < 2; mi++) {
                    MMA_BF16(acc[mi][2 * j],     ah[mi], bh[0], bh[1]);
                    MMA_BF16(acc[mi][2 * j],     ah[mi], bl[0], bl[1]);
                    MMA_BF16(acc[mi][2 * j],     al[mi], bh[0], bh[1]);
                    MMA_BF16(acc[mi][2 * j + 1], ah[mi], bh[2], bh[3]);
                    MMA_BF16(acc[mi][2 * j + 1], ah[mi], bl[2], bl[3]);
                    MMA_BF16(acc[mi][2 * j + 1], al[mi], bh[2], bh[3]);
                }
            }
        }
        st++; if (st >= 3) st = 0;
    }
    #undef ISSUE

    // ---- epilogue ----
    const int g = lane >> 2, q = lane & 3;
    #pragma unroll
    for (int mi = 0; mi < 2; mi++) {
        int rr0 = m0 + wm + mi * 16 + g;
        int rr1 = rr0 + 8;
        int tok0 = 0, tok1 = 0;
        float gw0 = 0.f, gw1 = 0.f;
        if (MODE == 3) {
            if (rr0 < cnt) { tok0 = g_tok[e * SEG + rr0]; gw0 = g_gw[e * SEG + rr0]; }
            if (rr1 < cnt) { tok1 = g_tok[e * SEG + rr1]; gw1 = g_gw[e * SEG + rr1]; }
        }
        #pragma unroll
        for (int ni = 0; ni < 8; ni++) {
            int c = n0 + wn + ni * 8 + 2 * q;
            float v0 = acc[mi][ni][0], v1 = acc[mi][ni][1];
            float v2 = acc[mi][ni][2], v3 = acc[mi][ni][3];
            if (MODE == 1) {
                bf16* Hh = sh ? g_hsh_h : g_hex_h + (size_t)e * SEG * DDIM;
                bf16* Hl = sh ? g_hsh_l : g_hex_l + (size_t)e * SEG * DDIM;
                if (rr0 < cnt) {
                    float f0 = fmaxf(v0, 0.f); f0 *= f0;
                    float f1 = fmaxf(v1, 0.f); f1 *= f1;
                    bf16 h0 = __float2bfloat16(f0), h1 = __float2bfloat16(f1);
                    bf16 l0 = __float2bfloat16(f0 - __bfloat162float(h0));
                    bf16 l1 = __float2bfloat16(f1 - __bfloat162float(h1));
                    bf16 hp[2] = {h0, h1}, lp[2] = {l0, l1};
                    *reinterpret_cast<uint32_t*>(Hh + (size_t)rr0 * DDIM + c) =
                        *reinterpret_cast<uint32_t*>(hp);
                    *reinterpret_cast<uint32_t*>(Hl + (size_t)rr0 * DDIM + c) =
                        *reinterpret_cast<uint32_t*>(lp);
                }
                if (rr1 < cnt) {
                    float f2 = fmaxf(v2, 0.f); f2 *= f2;
                    float f3 = fmaxf(v3, 0.f); f3 *= f3;
                    bf16 h2 = __float2bfloat16(f2), h3 = __float2bfloat16(f3);
                    bf16 l2 = __float2bfloat16(f2 - __bfloat162float(h2));
                    bf16 l3 = __float2bfloat16(f3 - __bfloat162float(h3));
                    bf16 hp[2] = {h2, h3}, lp[2] = {l2, l3};
                    *reinterpret_cast<uint32_t*>(Hh + (size_t)rr1 * DDIM + c) =
                        *reinterpret_cast<uint32_t*>(hp);
                    *reinterpret_cast<uint32_t*>(Hl + (size_t)rr1 * DDIM + c) =
                        *reinterpret_cast<uint32_t*>(lp);
                }
            } else if (MODE == 2) {
                *reinterpret_cast<float2*>(C + (size_t)rr0 * DDIM + c) =
                    make_float2(v0, v1);
                *reinterpret_cast<float2*>(C + (size_t)rr1 * DDIM + c) =
                    make_float2(v2, v3);
            } else {
                if (rr0 < cnt) {
                    atomicAdd(C + (size_t)tok0 * DDIM + c,     gw0 * v0);
                    atomicAdd(C + (size_t)tok0 * DDIM + c + 1, gw0 * v1);
                }
                if (rr1 < cnt) {
                    atomicAdd(C + (size_t)tok1 * DDIM + c,     gw1 * v2);
                    atomicAdd(C + (size_t)tok1 * DDIM + c + 1, gw1 * v3);
                }
            }
        }
    }
}

// ---------------- launch -----------------------------------------------------
extern "C" void kernel_launch(void* const* d_in, const int* in_sizes, int n_in,
                              void* d_out, int out_size) {
    const float* x      = (const float*)d_in[0];
    const float* gate_w = (const float*)d_in[1];
    const float* lbias  = (const float*)d_in[2];
    const float* w1     = (const float*)d_in[3];
    const float* w2     = (const float*)d_in[4];
    const float* cfc    = (const float*)d_in[5];
    const float* cproj  = (const float*)d_in[6];
    float* out = (float*)d_out;

    cudaFuncSetAttribute(gemm_mma<1>, cudaFuncAttributeMaxDynamicSharedMemorySize, SMEM_GEMM);
    cudaFuncSetAttribute(gemm_mma<2>, cudaFuncAttributeMaxDynamicSharedMemorySize, SMEM_GEMM);
    cudaFuncSetAttribute(gemm_mma<3>, cudaFuncAttributeMaxDynamicSharedMemorySize, SMEM_GEMM);

    bf16 *xh, *xl, *w1h, *w1l, *w2h, *w2l, *ch, *cl, *ph, *pl;
    cudaGetSymbolAddress((void**)&xh, g_xh);   cudaGetSymbolAddress((void**)&xl, g_xl);
    cudaGetSymbolAddress((void**)&w1h, g_w1h); cudaGetSymbolAddress((void**)&w1l, g_w1l);
    cudaGetSymbolAddress((void**)&w2h, g_w2h); cudaGetSymbolAddress((void**)&w2l, g_w2l);
    cudaGetSymbolAddress((void**)&ch, g_cfch); cudaGetSymbolAddress((void**)&cl, g_cfcl);
    cudaGetSymbolAddress((void**)&ph, g_cpjh); cudaGetSymbolAddress((void**)&pl, g_cpjl);

    zero_cnt_kernel<<<1, 32>>>();
    split_kernel<<<(NTOK * DDIM) / 1024, 256>>>(x, xh, xl);
    split_kernel<<<(NEXP * DDIM * DDIM) / 1024, 256>>>(w1, w1h, w1l);
    split_kernel<<<(NEXP * DDIM * DDIM) / 1024, 256>>>(w2, w2h, w2l);
    split_kernel<<<(DDIM * DDIM) / 1024, 256>>>(cfc, ch, cl);
    split_kernel<<<(DDIM * DDIM) / 1024, 256>>>(cproj, ph, pl);
    router_kernel<<<NTOK, 256>>>(x, gate_w, lbias);

    // phase 1 fused: y 0..15 shared GEMM1, y 16..143 expert GEMM1
    gemm_mma<1><<<dim3(8, 144), 256, SMEM_GEMM>>>(nullptr);
    // phase 2: shared GEMM2 writes out (covers poison), then expert scatter-add
    gemm_mma<2><<<dim3(8, 16), 256, SMEM_GEMM>>>(out);
    gemm_mma<3><<<dim3(8, 128), 256, SMEM_GEMM>>>(out);
}

// round 4
// speedup vs baseline: 2.6416x; 2.3245x over previous
#include <cuda_runtime.h>
#include <cuda_fp16.h>
#include <cstdint>

#define NTOK 2048
#define DDIM 1024
#define NEXP 8
#define SEG  2048

// ---------------- scratch (static device globals; no allocation) -------------
__device__ __half g_x16[NTOK * DDIM];
__device__ __half g_hsh16[NTOK * DDIM];
__device__ __half g_hex16[NEXP * SEG * DDIM];
__device__ __half g_w1_16[NEXP * DDIM * DDIM];
__device__ __half g_w2_16[NEXP * DDIM * DDIM];
__device__ __half g_cfc16[DDIM * DDIM];
__device__ __half g_cpj16[DDIM * DDIM];
__device__ int   g_cnt[NEXP];
__device__ int   g_tok[NEXP * SEG];
__device__ float g_gw[NEXP * SEG];

// region boundaries (elements)
#define C0 2097152u    // x
#define C1 10485760u   // + w1
#define C2 18874368u   // + w2
#define C3 19922944u   // + cfc
#define C4 20971520u   // + cproj

// ---------------- fused convert: fp32 -> fp16 for all operands ---------------
__global__ void convert_all(const float* __restrict__ x,
                            const float* __restrict__ w1,
                            const float* __restrict__ w2,
                            const float* __restrict__ cfc,
                            const float* __restrict__ cproj) {
    if (blockIdx.x == 0 && threadIdx.x < NEXP) g_cnt[threadIdx.x] = 0;
    size_t base = (size_t)blockIdx.x * 2048 + (size_t)threadIdx.x * 8;
    const float* src;
    __half* dst;
    size_t off;
    if (base < C0)      { src = x;     dst = g_x16;   off = base; }
    else if (base < C1) { src = w1;    dst = g_w1_16; off = base - C0; }
    else if (base < C2) { src = w2;    dst = g_w2_16; off = base - C1; }
    else if (base < C3) { src = cfc;   dst = g_cfc16; off = base - C2; }
    else                { src = cproj; dst = g_cpj16; off = base - C3; }
    float4 v0 = *reinterpret_cast<const float4*>(src + off);
    float4 v1 = *reinterpret_cast<const float4*>(src + off + 4);
    __half2 h[4];
    h[0] = __floats2half2_rn(v0.x, v0.y);
    h[1] = __floats2half2_rn(v0.z, v0.w);
    h[2] = __floats2half2_rn(v1.x, v1.y);
    h[3] = __floats2half2_rn(v1.z, v1.w);
    *reinterpret_cast<uint4*>(dst + off) = *reinterpret_cast<uint4*>(h);
}

// ---------------- router: exact fp32 logits, top-2, sigmoid gating -----------
__global__ void router_kernel(const float* __restrict__ x,
                              const float* __restrict__ gate_w,
                              const float* __restrict__ lb_bias) {
    __shared__ float lg[NEXP];
    int n = blockIdx.x;
    int e = threadIdx.x >> 5, lane = threadIdx.x & 31;
    const float* xr = x + (size_t)n * DDIM;
    const float* w  = gate_w + (size_t)e * DDIM;
    float s = 0.f;
    #pragma unroll 4
    for (int d = lane; d < DDIM; d += 32) s += xr[d] * w[d];
    #pragma unroll
    for (int o = 16; o; o >>= 1) s += __shfl_xor_sync(0xffffffffu, s, o);
    if (lane == 0) lg[e] = s;
    __syncthreads();
    if (threadIdx.x == 0) {
        float b1v = -1e30f; int b1 = 0;
        #pragma unroll
        for (int i = 0; i < NEXP; i++) {
            float v = lg[i] + lb_bias[i];
            if (v > b1v) { b1v = v; b1 = i; }
        }
        float b2v = -1e30f; int b2 = 0;
        #pragma unroll
        for (int i = 0; i < NEXP; i++) {
            if (i == b1) continue;
            float v = lg[i] + lb_bias[i];
            if (v > b2v) { b2v = v; b2 = i; }
        }
        float w1 = 1.f / (1.f + expf(-lg[b1]));
        float w2 = 1.f / (1.f + expf(-lg[b2]));
        float inv = 1.f / (w1 + w2 + 1e-6f);
        w1 *= inv; w2 *= inv;
        int p1 = atomicAdd(&g_cnt[b1], 1);
        g_tok[b1 * SEG + p1] = n; g_gw[b1 * SEG + p1] = w1;
        int p2 = atomicAdd(&g_cnt[b2], 1);
        g_tok[b2 * SEG + p2] = n; g_gw[b2 * SEG + p2] = w2;
    }
}

// ---------------- pipelined fp16 mma.sync GEMM -------------------------------
// BM=128, BN=128, BK=32, 3-stage cp.async, 8 warps, warp tile 32x64, 2 CTAs/SM.
// PHASE 1: y<16 shared GEMM1 (x*cfc), y>=16 expert GEMM1 (gather x * w1[e]);
//          epilogue relu^2 -> fp16 hidden.
// PHASE 2: y<16 shared GEMM2 (hsh*cproj), y>=16 expert GEMM2 (hex*w2[e]);
//          epilogue red.global.add.v2.f32 into pre-zeroed out (gw=1 for shared).

#define ROWB    80
#define REG_B   10240
#define STAGE_B 20480
#define SMEM_GEMM (3 * STAGE_B)

#define CP16(sm, gp) \
    asm volatile("cp.async.cg.shared.global [%0], [%1], 16;" \
                 :: "r"(sm), "l"(gp) : "memory")
#define CP_COMMIT() asm volatile("cp.async.commit_group;" ::: "memory")
#define CP_WAIT1()  asm volatile("cp.async.wait_group 1;" ::: "memory")

#define LDSM4(r, a) \
    asm volatile("ldmatrix.sync.aligned.m8n8.x4.shared.b16 {%0,%1,%2,%3}, [%4];" \
                 : "=r"((r)[0]), "=r"((r)[1]), "=r"((r)[2]), "=r"((r)[3]) \
                 : "r"(a))

#define MMA_F16(c, a, bb0, bb1)                                                \
    asm volatile(                                                              \
        "mma.sync.aligned.m16n8k16.row.col.f32.f16.f16.f32 "                   \
        "{%0,%1,%2,%3},{%4,%5,%6,%7},{%8,%9},{%0,%1,%2,%3};\n"                 \
        : "+f"((c)[0]), "+f"((c)[1]), "+f"((c)[2]), "+f"((c)[3])               \
        : "r"((a)[0]), "r"((a)[1]), "r"((a)[2]), "r"((a)[3]),                  \
          "r"(bb0), "r"(bb1))

__device__ __forceinline__ uint32_t smem_u32(const void* p) {
    uint32_t a;
    asm("{ .reg .u64 t; cvta.to.shared.u64 t, %1; cvt.u32.u64 %0, t; }"
        : "=r"(a) : "l"(p));
    return a;
}

__device__ __forceinline__ void red_add2(float* p, float a, float b) {
    asm volatile("red.global.add.v2.f32 [%0], {%1, %2};"
                 :: "l"(p), "f"(a), "f"(b) : "memory");
}

template <int PHASE>
__global__ __launch_bounds__(256, 2)
void gemm_mma(float* __restrict__ C) {
    extern __shared__ char dsm[];
    const int tid = threadIdx.x;
    const int wid = tid >> 5, lane = tid & 31;
    const int wm = (wid & 3) * 32, wn = (wid >> 2) * 64;

    const bool sh = (blockIdx.y < 16);
    int e = 0, m0, cnt;
    const __half *A, *B;
    if (sh) {
        m0 = blockIdx.y * 128;
        cnt = NTOK;
        if (PHASE == 1) { A = g_x16;   B = g_cfc16; }
        else            { A = g_hsh16; B = g_cpj16; }
    } else {
        int yb = blockIdx.y - 16;
        e = yb >> 4;
        m0 = (yb & 15) * 128;
        cnt = g_cnt[e];
        if (m0 >= cnt) return;
        size_t wo = (size_t)e * DDIM * DDIM;
        if (PHASE == 1) { A = g_x16; B = g_w1_16 + wo; }
        else { A = g_hex16 + (size_t)e * SEG * DDIM; B = g_w2_16 + wo; }
    }
    const int n0 = blockIdx.x * 128;

    // per-thread cp.async assignment: row lr, two 16B chunks
    const int lr = tid >> 1;
    const int lc0 = (tid & 1) * 2;
    const __half* pA;
    if (PHASE == 1 && !sh) {
        int rr = m0 + lr;
        int tok = g_tok[e * SEG + (rr < cnt ? rr : 0)];
        pA = g_x16 + (size_t)tok * DDIM;
    } else {
        pA = A + (size_t)(m0 + lr) * DDIM;
    }
    const __half* pB = B + (size_t)(n0 + lr) * DDIM;

    const uint32_t su = smem_u32(dsm);
    const uint32_t wbase = lr * ROWB + lc0 * 16;

    const uint32_t aoff = (uint32_t)((wm + (lane & 15)) * ROWB + (lane >> 4) * 16);
    const int brow = (lane & 7) | ((lane & 16) >> 1);
    const uint32_t boff = (uint32_t)((wn + brow) * ROWB + ((lane >> 3) & 1) * 16);

    float acc[2][8][4];
    #pragma unroll
    for (int mi = 0; mi < 2; mi++)
        #pragma unroll
        for (int ni = 0; ni < 8; ni++)
            #pragma unroll
            for (int j = 0; j < 4; j++) acc[mi][ni][j] = 0.f;

    #define ISSUE(kt, st) do {                                                 \
        uint32_t sb = su + (st) * STAGE_B + wbase;                             \
        const __half* ga = pA + (kt) * 32 + lc0 * 8;                           \
        CP16(sb, ga); CP16(sb + 16, ga + 8);                                   \
        const __half* gb = pB + (kt) * 32 + lc0 * 8;                           \
        CP16(sb + REG_B, gb); CP16(sb + REG_B + 16, gb + 8);                   \
    } while (0)

    ISSUE(0, 0); CP_COMMIT();
    ISSUE(1, 1); CP_COMMIT();

    int st = 0;
    for (int kt = 0; kt < 32; kt++) {
        CP_WAIT1();
        __syncthreads();
        int st2 = st + 2; if (st2 >= 3) st2 -= 3;
        if (kt < 30) ISSUE(kt + 2, st2);
        CP_COMMIT();

        const uint32_t sA = su + st * STAGE_B;
        const uint32_t sB = sA + REG_B;
        #pragma unroll
        for (int s = 0; s < 2; s++) {
            uint32_t ah[2][4];
            #pragma unroll
            for (int mi = 0; mi < 2; mi++)
                LDSM4(ah[mi], sA + aoff + mi * (16 * ROWB) + s * 32);
            #pragma unroll
            for (int j = 0; j < 4; j++) {
                uint32_t bh[4];
                LDSM4(bh, sB + boff + j * (16 * ROWB) + s * 32);
                #pragma unroll
                for (int mi = 0; mi < 2; mi++) {
                    MMA_F16(acc[mi][2 * j],     ah[mi], bh[0], bh[1]);
                    MMA_F16(acc[mi][2 * j + 1], ah[mi], bh[2], bh[3]);
                }
            }
        }
        st++; if (st >= 3) st = 0;
    }
    #undef ISSUE

    // ---- epilogue ----
    const int g = lane >> 2, q = lane & 3;
    #pragma unroll
    for (int mi = 0; mi < 2; mi++) {
        int rr0 = m0 + wm + mi * 16 + g;
        int rr1 = rr0 + 8;
        int tok0 = rr0, tok1 = rr1;
        float gw0 = 1.f, gw1 = 1.f;
        if (PHASE == 2 && !sh) {
            if (rr0 < cnt) { tok0 = g_tok[e * SEG + rr0]; gw0 = g_gw[e * SEG + rr0]; }
            if (rr1 < cnt) { tok1 = g_tok[e * SEG + rr1]; gw1 = g_gw[e * SEG + rr1]; }
        }
        #pragma unroll
        for (int ni = 0; ni < 8; ni++) {
            int c = n0 + wn + ni * 8 + 2 * q;
            float v0 = acc[mi][ni][0], v1 = acc[mi][ni][1];
            float v2 = acc[mi][ni][2], v3 = acc[mi][ni][3];
            if (PHASE == 1) {
                __half* H = sh ? g_hsh16 : g_hex16 + (size_t)e * SEG * DDIM;
                if (rr0 < cnt) {
                    float f0 = fmaxf(v0, 0.f); f0 *= f0;
                    float f1 = fmaxf(v1, 0.f); f1 *= f1;
                    *reinterpret_cast<__half2*>(H + (size_t)rr0 * DDIM + c) =
                        __floats2half2_rn(f0, f1);
                }
                if (rr1 < cnt) {
                    float f2 = fmaxf(v2, 0.f); f2 *= f2;
                    float f3 = fmaxf(v3, 0.f); f3 *= f3;
                    *reinterpret_cast<__half2*>(H + (size_t)rr1 * DDIM + c) =
                        __floats2half2_rn(f2, f3);
                }
            } else {
                if (rr0 < cnt)
                    red_add2(C + (size_t)tok0 * DDIM + c, gw0 * v0, gw0 * v1);
                if (rr1 < cnt)
                    red_add2(C + (size_t)tok1 * DDIM + c, gw1 * v2, gw1 * v3);
            }
        }
    }
}

// ---------------- launch -----------------------------------------------------
extern "C" void kernel_launch(void* const* d_in, const int* in_sizes, int n_in,
                              void* d_out, int out_size) {
    const float* x      = (const float*)d_in[0];
    const float* gate_w = (const float*)d_in[1];
    const float* lbias  = (const float*)d_in[2];
    const float* w1     = (const float*)d_in[3];
    const float* w2     = (const float*)d_in[4];
    const float* cfc    = (const float*)d_in[5];
    const float* cproj  = (const float*)d_in[6];
    float* out = (float*)d_out;

    cudaFuncSetAttribute(gemm_mma<1>, cudaFuncAttributeMaxDynamicSharedMemorySize, SMEM_GEMM);
    cudaFuncSetAttribute(gemm_mma<2>, cudaFuncAttributeMaxDynamicSharedMemorySize, SMEM_GEMM);

    convert_all<<<10240, 256>>>(x, w1, w2, cfc, cproj);
    router_kernel<<<NTOK, 256>>>(x, gate_w, lbias);
    cudaMemsetAsync(out, 0, (size_t)out_size * sizeof(float));

    // phase 1: y 0..15 shared GEMM1, y 16..143 expert GEMM1
    gemm_mma<1><<<dim3(8, 144), 256, SMEM_GEMM>>>(nullptr);
    // phase 2: fused shared GEMM2 + expert GEMM2, atomic accumulate into out
    gemm_mma<2><<<dim3(8, 144), 256, SMEM_GEMM>>>(out);
}